// round 3
// baseline (speedup 1.0000x reference)
#include <cuda_runtime.h>
#include <cuda_bf16.h>

// Problem shape (fixed by dataset):
//   S = 8192  source codes
//   G = 1024  groups
//   T = 4096  time segments (t0 sorted ascending)
//   E = 16384 events
// out[t, g] = sum over events e with start[e] <= t0[t] < end[e] of
//             rate[e] * weights[index[e]], grouped by group_id[index[e]].
//
// Since t0 is sorted, each event covers a contiguous index range [lo, hi):
//   lo = lower_bound(t0, start[e]),  hi = lower_bound(t0, end[e])
// => difference array on d_out + per-column inclusive prefix scan along T.

#define T_DIM 4096
#define G_DIM 1024

// ---------------------------------------------------------------------------
// Kernel 1: per-event binary search + scatter into difference array (d_out)
// ---------------------------------------------------------------------------
__global__ void scatter_diff_kernel(const int* __restrict__ index,
                                    const float* __restrict__ rate,
                                    const float* __restrict__ starttime,
                                    const float* __restrict__ endtime,
                                    const float* __restrict__ t0,
                                    const int* __restrict__ group_id,
                                    const float* __restrict__ weights,
                                    float* __restrict__ diff,
                                    int E)
{
    __shared__ float sh_t0[T_DIM];
    for (int i = threadIdx.x; i < T_DIM; i += blockDim.x)
        sh_t0[i] = t0[i];
    __syncthreads();

    int e = blockIdx.x * blockDim.x + threadIdx.x;
    if (e >= E) return;

    float st = starttime[e];
    float en = endtime[e];

    // lower_bound: first idx with t0[idx] >= x  (matches start <= t0 < end)
    int lo = 0, hi = T_DIM;
    while (lo < hi) {
        int m = (lo + hi) >> 1;
        if (sh_t0[m] < st) lo = m + 1; else hi = m;
    }
    int lo2 = lo, hi2 = T_DIM;
    while (lo2 < hi2) {
        int m = (lo2 + hi2) >> 1;
        if (sh_t0[m] < en) lo2 = m + 1; else hi2 = m;
    }
    // active range is [lo, lo2)
    if (lo >= lo2) return;

    int src = index[e];
    float w = rate[e] * weights[src];
    int g = group_id[src];

    atomicAdd(&diff[lo * G_DIM + g], w);
    if (lo2 < T_DIM)
        atomicAdd(&diff[lo2 * G_DIM + g], -w);
}

// ---------------------------------------------------------------------------
// Kernel 2: in-place inclusive prefix scan along T, per column g.
// Block handles 8 columns x full T. blockDim = (8, 32); each thread owns a
// 128-row chunk of one column. Two-phase: chunk sums -> block scan -> rewrite.
// ---------------------------------------------------------------------------
__global__ void __launch_bounds__(256)
scan_kernel(float* __restrict__ out)
{
    const int CH = T_DIM / 32;            // 128 rows per thread chunk
    int tx = threadIdx.x;                 // 0..7  column within tile
    int ty = threadIdx.y;                 // 0..31 chunk index
    int g  = blockIdx.x * 8 + tx;
    int tbase = ty * CH;

    // Phase 1: per-chunk sum
    float s = 0.0f;
    #pragma unroll 8
    for (int i = 0; i < CH; i++)
        s += out[(tbase + i) * G_DIM + g];

    __shared__ float sums[32][9];         // [chunk][col], padded
    sums[ty][tx] = s;
    __syncthreads();

    // Exclusive scan of the 32 chunk sums, per column (8 threads serial x32)
    if (ty == 0) {
        float acc = 0.0f;
        #pragma unroll
        for (int c = 0; c < 32; c++) {
            float v = sums[c][tx];
            sums[c][tx] = acc;
            acc += v;
        }
    }
    __syncthreads();

    // Phase 2: rewrite with running inclusive prefix + chunk offset
    float run = sums[ty][tx];
    #pragma unroll 8
    for (int i = 0; i < CH; i++) {
        int idx = (tbase + i) * G_DIM + g;
        run += out[idx];
        out[idx] = run;
    }
}

// ---------------------------------------------------------------------------
extern "C" void kernel_launch(void* const* d_in, const int* in_sizes, int n_in,
                              void* d_out, int out_size)
{
    const int*   index     = (const int*)  d_in[0];
    const float* rate      = (const float*)d_in[1];
    const float* starttime = (const float*)d_in[2];
    const float* endtime   = (const float*)d_in[3];
    const float* t0        = (const float*)d_in[4];
    const int*   group_id  = (const int*)  d_in[5];
    const float* weights   = (const float*)d_in[6];
    float*       out       = (float*)d_out;

    int E = in_sizes[0];

    // Zero the difference array (d_out doubles as diff, scanned in place)
    cudaMemsetAsync(d_out, 0, (size_t)out_size * sizeof(float), 0);

    // Scatter event contributions
    int threads = 256;
    int blocks  = (E + threads - 1) / threads;
    scatter_diff_kernel<<<blocks, threads>>>(index, rate, starttime, endtime,
                                             t0, group_id, weights, out, E);

    // Prefix scan along T for each group column
    dim3 bdim(8, 32);
    scan_kernel<<<G_DIM / 8, bdim>>>(out);
}

// round 4
// speedup vs baseline: 1.1126x; 1.1126x over previous
#include <cuda_runtime.h>
#include <cuda_bf16.h>

// Problem shape (fixed by dataset):
//   S = 8192  source codes
//   G = 1024  groups
//   T = 4096  time segments (t0 sorted ascending)
//   E = 16384 events
// out[t, g] = sum over events e with start[e] <= t0[t] < end[e] of
//             rate[e] * weights[index[e]], grouped by group_id[index[e]].
//
// Since t0 is sorted, each event covers a contiguous time-index range [lo,hi):
// difference array on d_out + per-column inclusive prefix scan along T.
// The scan is hierarchical (chunk sums -> scan of sums -> apply), fully
// float4-vectorized with warp-coalesced row access.

#define T_DIM 4096
#define G_DIM 1024
#define G4    (G_DIM / 4)      // 256 float4 columns
#define CH    16               // rows per chunk
#define NCH   (T_DIM / CH)     // 256 chunks

// Scratch: per-(chunk, float4-column) partial sums. 256*256*16B = 1 MB.
__device__ float4 g_partial[NCH][G4];

// ---------------------------------------------------------------------------
// Kernel 1: per-event binary search + scatter into difference array (d_out)
// ---------------------------------------------------------------------------
__global__ void scatter_diff_kernel(const int* __restrict__ index,
                                    const float* __restrict__ rate,
                                    const float* __restrict__ starttime,
                                    const float* __restrict__ endtime,
                                    const float* __restrict__ t0,
                                    const int* __restrict__ group_id,
                                    const float* __restrict__ weights,
                                    float* __restrict__ diff,
                                    int E)
{
    __shared__ float sh_t0[T_DIM];
    for (int i = threadIdx.x; i < T_DIM; i += blockDim.x)
        sh_t0[i] = t0[i];
    __syncthreads();

    int e = blockIdx.x * blockDim.x + threadIdx.x;
    if (e >= E) return;

    float st = starttime[e];
    float en = endtime[e];

    // lower_bound: first idx with t0[idx] >= x  (matches start <= t0 < end)
    int lo = 0, hi = T_DIM;
    while (lo < hi) {
        int m = (lo + hi) >> 1;
        if (sh_t0[m] < st) lo = m + 1; else hi = m;
    }
    int lo2 = lo, hi2 = T_DIM;
    while (lo2 < hi2) {
        int m = (lo2 + hi2) >> 1;
        if (sh_t0[m] < en) lo2 = m + 1; else hi2 = m;
    }
    // active range is [lo, lo2)
    if (lo >= lo2) return;

    int src = index[e];
    float w = rate[e] * weights[src];
    int g = group_id[src];

    atomicAdd(&diff[lo * G_DIM + g], w);
    if (lo2 < T_DIM)
        atomicAdd(&diff[lo2 * G_DIM + g], -w);
}

// ---------------------------------------------------------------------------
// Kernel 2: chunk sums. Block = one chunk (16 rows), thread = one float4 col.
// Warp reads 32 consecutive float4 per row -> perfectly coalesced 512B.
// ---------------------------------------------------------------------------
__global__ void __launch_bounds__(G4)
chunk_sum_kernel(const float4* __restrict__ diff)
{
    int j = threadIdx.x;           // float4 column 0..255
    int c = blockIdx.x;            // chunk 0..255
    const float4* p = diff + (size_t)c * CH * G4 + j;

    float4 s = make_float4(0.f, 0.f, 0.f, 0.f);
    #pragma unroll
    for (int r = 0; r < CH; r++) {
        float4 v = p[r * G4];
        s.x += v.x; s.y += v.y; s.z += v.z; s.w += v.w;
    }
    g_partial[c][j] = s;
}

// ---------------------------------------------------------------------------
// Kernel 3: scan the NCH chunk sums per float4 column; store EXCLUSIVE prefix.
// Block = one float4 column, blockDim = NCH, Hillis-Steele in shared.
// ---------------------------------------------------------------------------
__global__ void __launch_bounds__(NCH)
scan_partials_kernel()
{
    __shared__ float4 sh[NCH];
    int j = blockIdx.x;
    int c = threadIdx.x;

    float4 v = g_partial[c][j];
    sh[c] = v;
    __syncthreads();

    #pragma unroll
    for (int off = 1; off < NCH; off <<= 1) {
        float4 add = make_float4(0.f, 0.f, 0.f, 0.f);
        if (c >= off) add = sh[c - off];
        __syncthreads();
        sh[c].x += add.x; sh[c].y += add.y; sh[c].z += add.z; sh[c].w += add.w;
        __syncthreads();
    }

    float4 inc = sh[c];
    g_partial[c][j] = make_float4(inc.x - v.x, inc.y - v.y,
                                  inc.z - v.z, inc.w - v.w);
}

// ---------------------------------------------------------------------------
// Kernel 4: apply. Running inclusive sum within chunk, seeded by the
// exclusive chunk offset; in-place rewrite. Same access pattern as K2.
// ---------------------------------------------------------------------------
__global__ void __launch_bounds__(G4)
scan_apply_kernel(float4* __restrict__ out)
{
    int j = threadIdx.x;
    int c = blockIdx.x;
    float4 run = g_partial[c][j];
    float4* p = out + (size_t)c * CH * G4 + j;

    #pragma unroll
    for (int r = 0; r < CH; r++) {
        float4 v = p[r * G4];
        run.x += v.x; run.y += v.y; run.z += v.z; run.w += v.w;
        p[r * G4] = run;
    }
}

// ---------------------------------------------------------------------------
extern "C" void kernel_launch(void* const* d_in, const int* in_sizes, int n_in,
                              void* d_out, int out_size)
{
    const int*   index     = (const int*)  d_in[0];
    const float* rate      = (const float*)d_in[1];
    const float* starttime = (const float*)d_in[2];
    const float* endtime   = (const float*)d_in[3];
    const float* t0        = (const float*)d_in[4];
    const int*   group_id  = (const int*)  d_in[5];
    const float* weights   = (const float*)d_in[6];
    float*       out       = (float*)d_out;

    int E = in_sizes[0];

    // Zero the difference array (d_out doubles as diff, scanned in place)
    cudaMemsetAsync(d_out, 0, (size_t)out_size * sizeof(float), 0);

    // Scatter event contributions
    int threads = 256;
    int blocks  = (E + threads - 1) / threads;
    scatter_diff_kernel<<<blocks, threads>>>(index, rate, starttime, endtime,
                                             t0, group_id, weights, out, E);

    // Hierarchical prefix scan along T for each group column
    chunk_sum_kernel<<<NCH, G4>>>((const float4*)out);
    scan_partials_kernel<<<G4, NCH>>>();
    scan_apply_kernel<<<NCH, G4>>>((float4*)out);
}